// round 1
// baseline (speedup 1.0000x reference)
#include <cuda_runtime.h>
#include <math.h>

#define BB  2
#define SS  2048
#define DD  1024
#define HH  16
#define DKK 64
#define MM  (BB*SS)   // 4096 rows

// Scratch (allocation-free rule: __device__ globals)
__device__ float g_PE[SS*DKK];
__device__ float g_Q[MM*DD];
__device__ float g_Kraw[MM*DD];
__device__ float g_Ks[MM*DD];
__device__ float g_V[MM*DD];
__device__ float g_attn[MM*DD];
__device__ float g_Y[MM*DD];

// ---------------------------------------------------------------------------
// Sinusoidal positional embeddings  pe[s][dk], d = DK = 64
// ---------------------------------------------------------------------------
__global__ void pe_kernel() {
    int idx = blockIdx.x * blockDim.x + threadIdx.x;
    if (idx >= SS * DKK) return;
    int s  = idx >> 6;
    int dk = idx & 63;
    int i  = dk >> 1;
    // freq = exp(-(2i/64) * ln(10000))
    float freq = expf(-((float)(2 * i) / 64.0f) * 9.210340371976184f);
    float ang  = (float)s * freq;
    g_PE[idx]  = (dk & 1) ? cosf(ang) : sinf(ang);
}

// ---------------------------------------------------------------------------
// QKV projection: C = X @ W^T, written into [B,H,S,DK] layout.
// BM=BN=64, BK=16, 128 threads, 4x8 per-thread microtile.
// Smem tiles stored transposed: As[kk][m], Bs[kk][n] -> conflict-free LDS.
// Q gets PE added in the epilogue.
// ---------------------------------------------------------------------------
__global__ __launch_bounds__(128) void qkv_kernel(
    const float* __restrict__ X,
    const float* __restrict__ Wq,
    const float* __restrict__ Wk,
    const float* __restrict__ Wv)
{
    __shared__ float As[16][64];
    __shared__ float Bs[16][64];

    int z = blockIdx.z;
    const float* W   = (z == 0) ? Wq : ((z == 1) ? Wk : Wv);
    float*       out = (z == 0) ? g_Q : ((z == 1) ? g_Kraw : g_V);

    int m0 = blockIdx.y * 64;
    int n0 = blockIdx.x * 64;
    int t  = threadIdx.x;
    int tx = t & 7;        // 8 col groups
    int ty = t >> 3;       // 16 row groups

    float acc[4][8];
#pragma unroll
    for (int i = 0; i < 4; i++)
#pragma unroll
        for (int j = 0; j < 8; j++) acc[i][j] = 0.0f;

    int ldr = t >> 2;        // 0..31  (tile row)
    int ldc = (t & 3) * 4;   // float4 over kk

    for (int kb = 0; kb < 1024; kb += 16) {
#pragma unroll
        for (int p = 0; p < 2; p++) {
            int row = ldr + p * 32;
            float4 va = *(const float4*)(X + (size_t)(m0 + row) * 1024 + kb + ldc);
            As[ldc + 0][row] = va.x; As[ldc + 1][row] = va.y;
            As[ldc + 2][row] = va.z; As[ldc + 3][row] = va.w;
            float4 vb = *(const float4*)(W + (size_t)(n0 + row) * 1024 + kb + ldc);
            Bs[ldc + 0][row] = vb.x; Bs[ldc + 1][row] = vb.y;
            Bs[ldc + 2][row] = vb.z; Bs[ldc + 3][row] = vb.w;
        }
        __syncthreads();
#pragma unroll
        for (int kk = 0; kk < 16; kk++) {
            float a[4], w[8];
#pragma unroll
            for (int i = 0; i < 4; i++) a[i] = As[kk][ty * 4 + i];
#pragma unroll
            for (int j = 0; j < 8; j++) w[j] = Bs[kk][tx + 8 * j];
#pragma unroll
            for (int i = 0; i < 4; i++)
#pragma unroll
                for (int j = 0; j < 8; j++)
                    acc[i][j] = fmaf(a[i], w[j], acc[i][j]);
        }
        __syncthreads();
    }

#pragma unroll
    for (int i = 0; i < 4; i++) {
        int m = m0 + ty * 4 + i;
        int b = m >> 11;
        int s = m & 2047;
#pragma unroll
        for (int j = 0; j < 8; j++) {
            int n  = n0 + tx + 8 * j;
            int h  = n >> 6;
            int dk = n & 63;
            float v = acc[i][j];
            if (z == 0) v += g_PE[s * 64 + dk];
            out[(size_t)(((b << 4) + h) * 2048 + s) * 64 + dk] = v;
        }
    }
}

// ---------------------------------------------------------------------------
// EMA smear on K + PE add.  K'[t] = a[t-1]*K[t] + (1-a[t-1])*K[t-1], K'[0]=K[0]
// (2-tap filter over the ORIGINAL K — not a recurrence). Then + pe[s][dk].
// ---------------------------------------------------------------------------
__global__ void smear_kernel(const float* __restrict__ alpha) {
    int idx = blockIdx.x * blockDim.x + threadIdx.x;   // B*H*S*DK = 4M
    int dk = idx & 63;
    int s  = (idx >> 6) & 2047;
    int h  = (idx >> 17) & 15;
    float kc = g_Kraw[idx];
    float v;
    if (s == 0) {
        v = kc;
    } else {
        float a = 1.0f / (1.0f + expf(-alpha[h * 2047 + (s - 1)]));
        v = a * kc + (1.0f - a) * g_Kraw[idx - 64];
    }
    g_Ks[idx] = v + g_PE[s * 64 + dk];
}

// ---------------------------------------------------------------------------
// Causal flash attention, fp32. BM=BN=64, DK=64, 128 threads.
// Smem: Qt[dk][q] (16KB), KP[.][.] (Kt then Pt, 16KB), Vs[k][dk] (16KB) = 48KB.
// 4x8 per-thread microtile over (q rows, k cols) and (q rows, dk cols).
// Online softmax stats per q row, shared across 8-lane row groups.
// ---------------------------------------------------------------------------
__global__ __launch_bounds__(128) void attn_kernel() {
    __shared__ float Qt[64][64];
    __shared__ float KP[64][64];
    __shared__ float Vs[64][64];

    int qb = blockIdx.x * 64;
    int bh = blockIdx.y;
    const float* Qg = g_Q  + (size_t)bh * SS * DKK;
    const float* Kg = g_Ks + (size_t)bh * SS * DKK;
    const float* Vg = g_V  + (size_t)bh * SS * DKK;

    int t  = threadIdx.x;
    int tx = t & 7;
    int ty = t >> 3;
    int ldr = t >> 4;        // 0..7
    int ldc = (t & 15) * 4;  // float4 over dk

    // Load Q tile transposed
#pragma unroll
    for (int p = 0; p < 8; p++) {
        int row = ldr + p * 8;
        float4 v = *(const float4*)(Qg + (size_t)(qb + row) * 64 + ldc);
        Qt[ldc + 0][row] = v.x; Qt[ldc + 1][row] = v.y;
        Qt[ldc + 2][row] = v.z; Qt[ldc + 3][row] = v.w;
    }

    float o[4][8];
    float mr[4], lsum[4];
#pragma unroll
    for (int i = 0; i < 4; i++) {
        mr[i] = -1e30f; lsum[i] = 0.0f;
#pragma unroll
        for (int j = 0; j < 8; j++) o[i][j] = 0.0f;
    }

    int ntiles = blockIdx.x + 1;
    for (int tile = 0; tile < ntiles; tile++) {
        int kb = tile * 64;
        __syncthreads();   // previous PV reads of KP/Vs done; Qt ready (first iter)
#pragma unroll
        for (int p = 0; p < 8; p++) {
            int row = ldr + p * 8;
            float4 kv = *(const float4*)(Kg + (size_t)(kb + row) * 64 + ldc);
            KP[ldc + 0][row] = kv.x; KP[ldc + 1][row] = kv.y;
            KP[ldc + 2][row] = kv.z; KP[ldc + 3][row] = kv.w;
            float4 vv = *(const float4*)(Vg + (size_t)(kb + row) * 64 + ldc);
            *(float4*)(&Vs[row][ldc]) = vv;
        }
        __syncthreads();

        // S = Q K^T
        float sc[4][8];
#pragma unroll
        for (int i = 0; i < 4; i++)
#pragma unroll
            for (int j = 0; j < 8; j++) sc[i][j] = 0.0f;
#pragma unroll 8
        for (int kk = 0; kk < 64; kk++) {
            float a[4], bv[8];
#pragma unroll
            for (int i = 0; i < 4; i++) a[i] = Qt[kk][ty * 4 + i];
#pragma unroll
            for (int j = 0; j < 8; j++) bv[j] = KP[kk][tx + 8 * j];
#pragma unroll
            for (int i = 0; i < 4; i++)
#pragma unroll
                for (int j = 0; j < 8; j++)
                    sc[i][j] = fmaf(a[i], bv[j], sc[i][j]);
        }

        bool diag = (tile == blockIdx.x);
#pragma unroll
        for (int i = 0; i < 4; i++)
#pragma unroll
            for (int j = 0; j < 8; j++) {
                float v = sc[i][j] * 0.125f;
                if (diag && (tx + 8 * j > ty * 4 + i)) v = -1e30f;
                sc[i][j] = v;
            }

        // Online softmax per q row (row group = 8 lanes sharing ty)
#pragma unroll
        for (int i = 0; i < 4; i++) {
            float mx = sc[i][0];
#pragma unroll
            for (int j = 1; j < 8; j++) mx = fmaxf(mx, sc[i][j]);
            mx = fmaxf(mx, __shfl_xor_sync(0xffffffffu, mx, 1));
            mx = fmaxf(mx, __shfl_xor_sync(0xffffffffu, mx, 2));
            mx = fmaxf(mx, __shfl_xor_sync(0xffffffffu, mx, 4));
            float mnew = fmaxf(mr[i], mx);
            float corr = __expf(mr[i] - mnew);
            mr[i] = mnew;
            float rs = 0.0f;
#pragma unroll
            for (int j = 0; j < 8; j++) {
                float p = __expf(sc[i][j] - mnew);
                sc[i][j] = p;
                rs += p;
            }
            rs += __shfl_xor_sync(0xffffffffu, rs, 1);
            rs += __shfl_xor_sync(0xffffffffu, rs, 2);
            rs += __shfl_xor_sync(0xffffffffu, rs, 4);
            lsum[i] = lsum[i] * corr + rs;
#pragma unroll
            for (int j = 0; j < 8; j++) o[i][j] *= corr;
        }

        __syncthreads();    // all warps done reading KP as Kt
        // Write P transposed: Pt[key][q]
#pragma unroll
        for (int i = 0; i < 4; i++)
#pragma unroll
            for (int j = 0; j < 8; j++)
                KP[tx + 8 * j][ty * 4 + i] = sc[i][j];
        __syncthreads();

        // O += P V
#pragma unroll 8
        for (int kk = 0; kk < 64; kk++) {
            float pv[4], vv[8];
#pragma unroll
            for (int i = 0; i < 4; i++) pv[i] = KP[kk][ty * 4 + i];
#pragma unroll
            for (int j = 0; j < 8; j++) vv[j] = Vs[kk][tx + 8 * j];
#pragma unroll
            for (int i = 0; i < 4; i++)
#pragma unroll
                for (int j = 0; j < 8; j++)
                    o[i][j] = fmaf(pv[i], vv[j], o[i][j]);
        }
    }

    // Write O / l in [B,S,H*DK] row-major for the output projection
    int b = bh >> 4, h = bh & 15;
#pragma unroll
    for (int i = 0; i < 4; i++) {
        float inv = 1.0f / lsum[i];
        int srow = qb + ty * 4 + i;
#pragma unroll
        for (int j = 0; j < 8; j++)
            g_attn[(size_t)(b * SS + srow) * DD + h * 64 + tx + 8 * j] = o[i][j] * inv;
    }
}

// ---------------------------------------------------------------------------
// Output projection: Y = attn @ Wo^T + X   (same SGEMM structure)
// ---------------------------------------------------------------------------
__global__ __launch_bounds__(128) void oproj_kernel(
    const float* __restrict__ Wo,
    const float* __restrict__ X)
{
    __shared__ float As[16][64];
    __shared__ float Bs[16][64];

    int m0 = blockIdx.y * 64;
    int n0 = blockIdx.x * 64;
    int t  = threadIdx.x;
    int tx = t & 7;
    int ty = t >> 3;

    float acc[4][8];
#pragma unroll
    for (int i = 0; i < 4; i++)
#pragma unroll
        for (int j = 0; j < 8; j++) acc[i][j] = 0.0f;

    int ldr = t >> 2;
    int ldc = (t & 3) * 4;

    for (int kb = 0; kb < 1024; kb += 16) {
#pragma unroll
        for (int p = 0; p < 2; p++) {
            int row = ldr + p * 32;
            float4 va = *(const float4*)(g_attn + (size_t)(m0 + row) * 1024 + kb + ldc);
            As[ldc + 0][row] = va.x; As[ldc + 1][row] = va.y;
            As[ldc + 2][row] = va.z; As[ldc + 3][row] = va.w;
            float4 vb = *(const float4*)(Wo + (size_t)(n0 + row) * 1024 + kb + ldc);
            Bs[ldc + 0][row] = vb.x; Bs[ldc + 1][row] = vb.y;
            Bs[ldc + 2][row] = vb.z; Bs[ldc + 3][row] = vb.w;
        }
        __syncthreads();
#pragma unroll
        for (int kk = 0; kk < 16; kk++) {
            float a[4], w[8];
#pragma unroll
            for (int i = 0; i < 4; i++) a[i] = As[kk][ty * 4 + i];
#pragma unroll
            for (int j = 0; j < 8; j++) w[j] = Bs[kk][tx + 8 * j];
#pragma unroll
            for (int i = 0; i < 4; i++)
#pragma unroll
                for (int j = 0; j < 8; j++)
                    acc[i][j] = fmaf(a[i], w[j], acc[i][j]);
        }
        __syncthreads();
    }

#pragma unroll
    for (int i = 0; i < 4; i++) {
        int m = m0 + ty * 4 + i;
#pragma unroll
        for (int j = 0; j < 8; j++) {
            int n = n0 + tx + 8 * j;
            g_Y[(size_t)m * 1024 + n] = acc[i][j] + X[(size_t)m * 1024 + n];
        }
    }
}

// ---------------------------------------------------------------------------
// LayerNorm over D=1024 per row, 256 threads/row, two-pass in registers.
// ---------------------------------------------------------------------------
__global__ void ln_kernel(const float* __restrict__ gamma,
                          const float* __restrict__ beta,
                          float* __restrict__ out)
{
    int row = blockIdx.x;
    int t   = threadIdx.x;
    const float* y = g_Y + (size_t)row * 1024;

    float x[4];
    float s = 0.0f;
#pragma unroll
    for (int u = 0; u < 4; u++) { x[u] = y[t + 256 * u]; s += x[u]; }

    __shared__ float red[32];
#pragma unroll
    for (int off = 16; off; off >>= 1) s += __shfl_xor_sync(0xffffffffu, s, off);
    if ((t & 31) == 0) red[t >> 5] = s;
    __syncthreads();
    if (t == 0) {
        float tot = 0.0f;
        for (int w = 0; w < 8; w++) tot += red[w];
        red[8] = tot;
    }
    __syncthreads();
    float mean = red[8] * (1.0f / 1024.0f);

    float vs = 0.0f;
#pragma unroll
    for (int u = 0; u < 4; u++) { float d = x[u] - mean; vs += d * d; }
#pragma unroll
    for (int off = 16; off; off >>= 1) vs += __shfl_xor_sync(0xffffffffu, vs, off);
    if ((t & 31) == 0) red[16 + (t >> 5)] = vs;
    __syncthreads();
    if (t == 0) {
        float tot = 0.0f;
        for (int w = 0; w < 8; w++) tot += red[16 + w];
        red[24] = tot;
    }
    __syncthreads();
    float var  = red[24] * (1.0f / 1024.0f);
    float rstd = rsqrtf(var + 1e-5f);

#pragma unroll
    for (int u = 0; u < 4; u++) {
        int c = t + 256 * u;
        out[(size_t)row * 1024 + c] = (x[u] - mean) * rstd * gamma[c] + beta[c];
    }
}

// ---------------------------------------------------------------------------
extern "C" void kernel_launch(void* const* d_in, const int* in_sizes, int n_in,
                              void* d_out, int out_size)
{
    const float* X     = (const float*)d_in[0];
    const float* Wq    = (const float*)d_in[1];
    const float* Wk    = (const float*)d_in[2];
    const float* Wv    = (const float*)d_in[3];
    const float* Wo    = (const float*)d_in[4];
    const float* alpha = (const float*)d_in[5];
    const float* lns   = (const float*)d_in[6];
    const float* lnb   = (const float*)d_in[7];
    float* out = (float*)d_out;

    pe_kernel<<<(SS * DKK + 255) / 256, 256>>>();
    qkv_kernel<<<dim3(16, 64, 3), 128>>>(X, Wq, Wk, Wv);
    smear_kernel<<<(MM * DD) / 256, 256>>>(alpha);
    attn_kernel<<<dim3(32, 32), 128>>>();
    oproj_kernel<<<dim3(16, 64), 128>>>(Wo, X);
    ln_kernel<<<MM, 256>>>(lns, lnb, out);
}

// round 3
// speedup vs baseline: 1.4370x; 1.4370x over previous
#include <cuda_runtime.h>
#include <cuda_bf16.h>
#include <math.h>
#include <stdint.h>

#define BB  2
#define SS  2048
#define DD  1024
#define HH  16
#define DKK 64
#define MM  (BB*SS)   // 4096 rows

// ---------------------------------------------------------------------------
// Scratch (allocation-free rule: __device__ globals)
// ---------------------------------------------------------------------------
__device__ __align__(16) float g_PE[SS*DKK];
__device__ __align__(16) float g_Q[MM*DD];
__device__ __align__(16) float g_Kraw[MM*DD];
__device__ __align__(16) float g_Ks[MM*DD];
__device__ __align__(16) float g_V[MM*DD];
__device__ __align__(16) float g_attn[MM*DD];
__device__ __align__(16) float g_Y[MM*DD];

// bf16 hi/lo split operands
__device__ __align__(16) __nv_bfloat16 g_Xhi[MM*DD];
__device__ __align__(16) __nv_bfloat16 g_Xlo[MM*DD];
__device__ __align__(16) __nv_bfloat16 g_Wh[3*DD*DD];
__device__ __align__(16) __nv_bfloat16 g_Wl[3*DD*DD];
__device__ __align__(16) __nv_bfloat16 g_Woh[DD*DD];
__device__ __align__(16) __nv_bfloat16 g_Wol[DD*DD];
__device__ __align__(16) __nv_bfloat16 g_Ahi[MM*DD];
__device__ __align__(16) __nv_bfloat16 g_Alo[MM*DD];

// ---------------------------------------------------------------------------
// PTX helpers (baseline sm_103-safe: ldmatrix / mma.sync / cp.async only)
// ---------------------------------------------------------------------------
__device__ __forceinline__ uint32_t smem_u32(const void* p) {
    uint32_t a;
    asm("{ .reg .u64 t; cvta.to.shared.u64 t, %1; cvt.u32.u64 %0, t; }"
        : "=r"(a) : "l"(p));
    return a;
}

#define CPA16(dst, src) \
    asm volatile("cp.async.cg.shared.global [%0], [%1], 16;" :: "r"(dst), "l"(src) : "memory")
#define CPA_COMMIT() asm volatile("cp.async.commit_group;" ::: "memory")
#define CPA_WAIT1()  asm volatile("cp.async.wait_group 1;" ::: "memory")
#define CPA_WAIT0()  asm volatile("cp.async.wait_group 0;" ::: "memory")

__device__ __forceinline__ void ldsm_x4(uint32_t* r, uint32_t addr) {
    asm volatile("ldmatrix.sync.aligned.m8n8.x4.shared.b16 {%0,%1,%2,%3}, [%4];"
                 : "=r"(r[0]), "=r"(r[1]), "=r"(r[2]), "=r"(r[3]) : "r"(addr));
}

__device__ __forceinline__ void mma_bf16(float* c, const uint32_t* a, const uint32_t* b) {
    asm volatile(
        "mma.sync.aligned.m16n8k16.row.col.f32.bf16.bf16.f32 "
        "{%0,%1,%2,%3}, {%4,%5,%6,%7}, {%8,%9}, {%0,%1,%2,%3};"
        : "+f"(c[0]), "+f"(c[1]), "+f"(c[2]), "+f"(c[3])
        : "r"(a[0]), "r"(a[1]), "r"(a[2]), "r"(a[3]), "r"(b[0]), "r"(b[1]));
}

// ---------------------------------------------------------------------------
// Sinusoidal positional embeddings
// ---------------------------------------------------------------------------
__global__ void pe_kernel() {
    int idx = blockIdx.x * blockDim.x + threadIdx.x;
    if (idx >= SS * DKK) return;
    int s  = idx >> 6;
    int dk = idx & 63;
    int i  = dk >> 1;
    float freq = expf(-((float)(2 * i) / 64.0f) * 9.210340371976184f);
    float ang  = (float)s * freq;
    g_PE[idx]  = (dk & 1) ? cosf(ang) : sinf(ang);
}

// ---------------------------------------------------------------------------
// fp32 -> bf16 hi/lo split
// ---------------------------------------------------------------------------
__global__ void conv_kernel(const float* __restrict__ src,
                            __nv_bfloat16* __restrict__ hi,
                            __nv_bfloat16* __restrict__ lo, int n4) {
    int i = blockIdx.x * blockDim.x + threadIdx.x;
    if (i >= n4) return;
    float4 v = ((const float4*)src)[i];
    __nv_bfloat16 h0 = __float2bfloat16(v.x);
    __nv_bfloat16 h1 = __float2bfloat16(v.y);
    __nv_bfloat16 h2 = __float2bfloat16(v.z);
    __nv_bfloat16 h3 = __float2bfloat16(v.w);
    __nv_bfloat16 l0 = __float2bfloat16(v.x - __bfloat162float(h0));
    __nv_bfloat16 l1 = __float2bfloat16(v.y - __bfloat162float(h1));
    __nv_bfloat16 l2 = __float2bfloat16(v.z - __bfloat162float(h2));
    __nv_bfloat16 l3 = __float2bfloat16(v.w - __bfloat162float(h3));
    __nv_bfloat162* hp = (__nv_bfloat162*)hi;
    __nv_bfloat162* lp = (__nv_bfloat162*)lo;
    hp[2*i]   = __nv_bfloat162(h0, h1);
    hp[2*i+1] = __nv_bfloat162(h2, h3);
    lp[2*i]   = __nv_bfloat162(l0, l1);
    lp[2*i+1] = __nv_bfloat162(l2, l3);
}

// ---------------------------------------------------------------------------
// bf16x3 HMMA GEMM mainloop: acc[128x128] = A[128x1024] @ B[128x1024]^T
// 256 threads, BK=32, 2-stage cp.async. Warp w = (wm = w>>1, wn = w&1)
// owns a 32x64 tile: 2 m16 x 8 n8 fragments. 3 products: AhBh + AhBl + AlBh.
// Smem per stage: 4 matrices x 128 rows x 80B (32 bf16 + 8 pad) = 40960B.
// ---------------------------------------------------------------------------
#define ROWB 80
#define MATB (128 * ROWB)        // 10240
#define STG  (4 * MATB)          // 40960
#define DYN_SMEM (2 * STG)       // 81920

__device__ __forceinline__ void mma_gemm(
    const __nv_bfloat16* __restrict__ Ah, const __nv_bfloat16* __restrict__ Al,
    const __nv_bfloat16* __restrict__ Bh, const __nv_bfloat16* __restrict__ Bl,
    char* dyn, float acc[2][8][4])
{
    int t    = threadIdx.x;
    int lane = t & 31;
    int wid  = t >> 5;
    int wm   = wid >> 1;            // 0..3
    int wn   = wid & 1;             // 0..1
    uint32_t sbase = smem_u32(dyn);

    const char* mats[4] = {(const char*)Ah, (const char*)Al,
                           (const char*)Bh, (const char*)Bl};

#pragma unroll
    for (int tm = 0; tm < 2; tm++)
#pragma unroll
        for (int tn = 0; tn < 8; tn++)
#pragma unroll
            for (int u = 0; u < 4; u++) acc[tm][tn][u] = 0.0f;

    // per-thread copy assignment: 8 x 16B
    int idx0 = t * 8;

    auto load_stage = [&](int st, int kb) {
        uint32_t stb = sbase + st * STG;
#pragma unroll
        for (int q = 0; q < 8; q++) {
            int idx = idx0 + q;
            int mat = idx >> 9;             // 512 chunks per matrix
            int r   = (idx >> 2) & 127;
            int c16 = idx & 3;
            uint32_t dst = stb + mat * MATB + r * ROWB + c16 * 16;
            const char* src = mats[mat] + ((size_t)r * 1024 + kb + c16 * 8) * 2;
            CPA16(dst, src);
        }
        CPA_COMMIT();
    };

    // ldmatrix address offsets (within a matrix block, given k0)
    int a_row = wm * 32 + (lane & 15);              // + 16*tm
    int b_row = wn * 64 + (lane & 7) + 8 * (lane >> 4);  // + 16*tp

    load_stage(0, 0);

    for (int it = 0; it < 32; it++) {
        int st = it & 1;
        if (it + 1 < 32) {
            load_stage(st ^ 1, (it + 1) * 32);
            CPA_WAIT1();
        } else {
            CPA_WAIT0();
        }
        __syncthreads();

        uint32_t stb = sbase + st * STG;
#pragma unroll
        for (int ks = 0; ks < 2; ks++) {
            int k0 = ks * 16;
            uint32_t aH[2][4], aL[2][4], bH[8][2], bL[8][2];
            int a_col = (k0 + 8 * (lane >> 4)) * 2;
            int b_col = (k0 + 8 * ((lane >> 3) & 1)) * 2;
#pragma unroll
            for (int tm = 0; tm < 2; tm++) {
                uint32_t off = (uint32_t)((a_row + 16 * tm) * ROWB + a_col);
                ldsm_x4(aH[tm], stb + 0 * MATB + off);
                ldsm_x4(aL[tm], stb + 1 * MATB + off);
            }
#pragma unroll
            for (int tp = 0; tp < 4; tp++) {
                uint32_t off = (uint32_t)((b_row + 16 * tp) * ROWB + b_col);
                ldsm_x4(&bH[2 * tp][0], stb + 2 * MATB + off);
                ldsm_x4(&bL[2 * tp][0], stb + 3 * MATB + off);
            }
#pragma unroll
            for (int tm = 0; tm < 2; tm++)
#pragma unroll
                for (int tn = 0; tn < 8; tn++) {
                    mma_bf16(acc[tm][tn], aH[tm], bH[tn]);
                    mma_bf16(acc[tm][tn], aH[tm], bL[tn]);
                    mma_bf16(acc[tm][tn], aL[tm], bH[tn]);
                }
        }
        __syncthreads();
    }
}

// ---------------------------------------------------------------------------
// QKV GEMM: z = 0/1/2 -> Q/K/V, head-split output layout, Q += PE
// ---------------------------------------------------------------------------
__global__ __launch_bounds__(256) void qkv_mma() {
    extern __shared__ char dyn[];
    float acc[2][8][4];

    int z  = blockIdx.z;
    int m0 = blockIdx.y * 128;
    int n0 = blockIdx.x * 128;

    mma_gemm(g_Xhi + (size_t)m0 * 1024, g_Xlo + (size_t)m0 * 1024,
             g_Wh + (size_t)z * DD * DD + (size_t)n0 * 1024,
             g_Wl + (size_t)z * DD * DD + (size_t)n0 * 1024,
             dyn, acc);

    float* out = (z == 0) ? g_Q : ((z == 1) ? g_Kraw : g_V);
    int t = threadIdx.x, lane = t & 31, wid = t >> 5;
    int wm = wid >> 1, wn = wid & 1;
#pragma unroll
    for (int tm = 0; tm < 2; tm++)
#pragma unroll
        for (int tn = 0; tn < 8; tn++) {
            int c  = n0 + wn * 64 + tn * 8 + (lane & 3) * 2;
            int h  = c >> 6, dk = c & 63;
#pragma unroll
            for (int half = 0; half < 2; half++) {
                int m = m0 + wm * 32 + tm * 16 + (lane >> 2) + 8 * half;
                int b = m >> 11, s = m & 2047;
                float2 v;
                v.x = acc[tm][tn][2 * half + 0];
                v.y = acc[tm][tn][2 * half + 1];
                if (z == 0) {
                    float2 pe = *(const float2*)&g_PE[s * 64 + dk];
                    v.x += pe.x; v.y += pe.y;
                }
                *(float2*)&out[((size_t)((b * 16 + h) * 2048 + s)) * 64 + dk] = v;
            }
        }
}

// ---------------------------------------------------------------------------
// Output projection GEMM: Y = attn @ Wo^T + X
// ---------------------------------------------------------------------------
__global__ __launch_bounds__(256) void oproj_mma(const float* __restrict__ X) {
    extern __shared__ char dyn[];
    float acc[2][8][4];

    int m0 = blockIdx.y * 128;
    int n0 = blockIdx.x * 128;

    mma_gemm(g_Ahi + (size_t)m0 * 1024, g_Alo + (size_t)m0 * 1024,
             g_Woh + (size_t)n0 * 1024, g_Wol + (size_t)n0 * 1024,
             dyn, acc);

    int t = threadIdx.x, lane = t & 31, wid = t >> 5;
    int wm = wid >> 1, wn = wid & 1;
#pragma unroll
    for (int tm = 0; tm < 2; tm++)
#pragma unroll
        for (int tn = 0; tn < 8; tn++) {
            int c = n0 + wn * 64 + tn * 8 + (lane & 3) * 2;
#pragma unroll
            for (int half = 0; half < 2; half++) {
                int m = m0 + wm * 32 + tm * 16 + (lane >> 2) + 8 * half;
                float2 xr = *(const float2*)&X[(size_t)m * 1024 + c];
                float2 v;
                v.x = acc[tm][tn][2 * half + 0] + xr.x;
                v.y = acc[tm][tn][2 * half + 1] + xr.y;
                *(float2*)&g_Y[(size_t)m * 1024 + c] = v;
            }
        }
}

// ---------------------------------------------------------------------------
// EMA smear on K + PE add (2-tap filter over the ORIGINAL K)
// ---------------------------------------------------------------------------
__global__ void smear_kernel(const float* __restrict__ alpha) {
    int idx = blockIdx.x * blockDim.x + threadIdx.x;
    int dk = idx & 63;
    int s  = (idx >> 6) & 2047;
    int h  = (idx >> 17) & 15;
    float kc = g_Kraw[idx];
    float v;
    if (s == 0) {
        v = kc;
    } else {
        float a = 1.0f / (1.0f + expf(-alpha[h * 2047 + (s - 1)]));
        v = a * kc + (1.0f - a) * g_Kraw[idx - 64];
    }
    g_Ks[idx] = v + g_PE[s * 64 + dk];
}

// ---------------------------------------------------------------------------
// Causal flash attention, fp32. BM=BN=64, DK=64, 128 threads. (unchanged)
// ---------------------------------------------------------------------------
__global__ __launch_bounds__(128) void attn_kernel() {
    __shared__ float Qt[64][64];
    __shared__ float KP[64][64];
    __shared__ float Vs[64][64];

    int qb = blockIdx.x * 64;
    int bh = blockIdx.y;
    const float* Qg = g_Q  + (size_t)bh * SS * DKK;
    const float* Kg = g_Ks + (size_t)bh * SS * DKK;
    const float* Vg = g_V  + (size_t)bh * SS * DKK;

    int t  = threadIdx.x;
    int tx = t & 7;
    int ty = t >> 3;
    int ldr = t >> 4;
    int ldc = (t & 15) * 4;

#pragma unroll
    for (int p = 0; p < 8; p++) {
        int row = ldr + p * 8;
        float4 v = *(const float4*)(Qg + (size_t)(qb + row) * 64 + ldc);
        Qt[ldc + 0][row] = v.x; Qt[ldc + 1][row] = v.y;
        Qt[ldc + 2][row] = v.z; Qt[ldc + 3][row] = v.w;
    }

    float o[4][8];
    float mr[4], lsum[4];
#pragma unroll
    for (int i = 0; i < 4; i++) {
        mr[i] = -1e30f; lsum[i] = 0.0f;
#pragma unroll
        for (int j = 0; j < 8; j++) o[i][j] = 0.0f;
    }

    int ntiles = blockIdx.x + 1;
    for (int tile = 0; tile < ntiles; tile++) {
        int kb = tile * 64;
        __syncthreads();
#pragma unroll
        for (int p = 0; p < 8; p++) {
            int row = ldr + p * 8;
            float4 kv = *(const float4*)(Kg + (size_t)(kb + row) * 64 + ldc);
            KP[ldc + 0][row] = kv.x; KP[ldc + 1][row] = kv.y;
            KP[ldc + 2][row] = kv.z; KP[ldc + 3][row] = kv.w;
            float4 vv = *(const float4*)(Vg + (size_t)(kb + row) * 64 + ldc);
            *(float4*)(&Vs[row][ldc]) = vv;
        }
        __syncthreads();

        float sc[4][8];
#pragma unroll
        for (int i = 0; i < 4; i++)
#pragma unroll
            for (int j = 0; j < 8; j++) sc[i][j] = 0.0f;
#pragma unroll 8
        for (int kk = 0; kk < 64; kk++) {
            float a[4], bv[8];
#pragma unroll
            for (int i = 0; i < 4; i++) a[i] = Qt[kk][ty * 4 + i];
#pragma unroll
            for (int j = 0; j < 8; j++) bv[j] = KP[kk][tx + 8 * j];
#pragma unroll
            for (int i = 0; i < 4; i++)
#pragma unroll
                for (int j = 0; j < 8; j++)
                    sc[i][j] = fmaf(a[i], bv[j], sc[i][j]);
        }

        bool diag = (tile == blockIdx.x);
#pragma unroll
        for (int i = 0; i < 4; i++)
#pragma unroll
            for (int j = 0; j < 8; j++) {
                float v = sc[i][j] * 0.125f;
                if (diag && (tx + 8 * j > ty * 4 + i)) v = -1e30f;
                sc[i][j] = v;
            }

#pragma unroll
        for (int i = 0; i < 4; i++) {
            float mx = sc[i][0];
#pragma unroll
            for (int j = 1; j < 8; j++) mx = fmaxf(mx, sc[i][j]);
            mx = fmaxf(mx, __shfl_xor_sync(0xffffffffu, mx, 1));
            mx = fmaxf(mx, __shfl_xor_sync(0xffffffffu, mx, 2));
            mx = fmaxf(mx, __shfl_xor_sync(0xffffffffu, mx, 4));
            float mnew = fmaxf(mr[i], mx);
            float corr = __expf(mr[i] - mnew);
            mr[i] = mnew;
            float rs = 0.0f;
#pragma unroll
            for (int j = 0; j < 8; j++) {
                float p = __expf(sc[i][j] - mnew);
                sc[i][j] = p;
                rs += p;
            }
            rs += __shfl_xor_sync(0xffffffffu, rs, 1);
            rs += __shfl_xor_sync(0xffffffffu, rs, 2);
            rs += __shfl_xor_sync(0xffffffffu, rs, 4);
            lsum[i] = lsum[i] * corr + rs;
#pragma unroll
            for (int j = 0; j < 8; j++) o[i][j] *= corr;
        }

        __syncthreads();
#pragma unroll
        for (int i = 0; i < 4; i++)
#pragma unroll
            for (int j = 0; j < 8; j++)
                KP[tx + 8 * j][ty * 4 + i] = sc[i][j];
        __syncthreads();

#pragma unroll 8
        for (int kk = 0; kk < 64; kk++) {
            float pv[4], vv[8];
#pragma unroll
            for (int i = 0; i < 4; i++) pv[i] = KP[kk][ty * 4 + i];
#pragma unroll
            for (int j = 0; j < 8; j++) vv[j] = Vs[kk][tx + 8 * j];
#pragma unroll
            for (int i = 0; i < 4; i++)
#pragma unroll
                for (int j = 0; j < 8; j++)
                    o[i][j] = fmaf(pv[i], vv[j], o[i][j]);
        }
    }

    int b = bh >> 4, h = bh & 15;
#pragma unroll
    for (int i = 0; i < 4; i++) {
        float inv = 1.0f / lsum[i];
        int srow = qb + ty * 4 + i;
#pragma unroll
        for (int j = 0; j < 8; j++)
            g_attn[(size_t)(b * SS + srow) * DD + h * 64 + tx + 8 * j] = o[i][j] * inv;
    }
}

// ---------------------------------------------------------------------------
// LayerNorm over D=1024 per row (unchanged)
// ---------------------------------------------------------------------------
__global__ void ln_kernel(const float* __restrict__ gamma,
                          const float* __restrict__ beta,
                          float* __restrict__ out)
{
    int row = blockIdx.x;
    int t   = threadIdx.x;
    const float* y = g_Y + (size_t)row * 1024;

    float x[4];
    float s = 0.0f;
#pragma unroll
    for (int u = 0; u < 4; u++) { x[u] = y[t + 256 * u]; s += x[u]; }

    __shared__ float red[32];
#pragma unroll
    for (int off = 16; off; off >>= 1) s += __shfl_xor_sync(0xffffffffu, s, off);
    if ((t & 31) == 0) red[t >> 5] = s;
    __syncthreads();
    if (t == 0) {
        float tot = 0.0f;
        for (int w = 0; w < 8; w++) tot += red[w];
        red[8] = tot;
    }
    __syncthreads();
    float mean = red[8] * (1.0f / 1024.0f);

    float vs = 0.0f;
#pragma unroll
    for (int u = 0; u < 4; u++) { float d = x[u] - mean; vs += d * d; }
#pragma unroll
    for (int off = 16; off; off >>= 1) vs += __shfl_xor_sync(0xffffffffu, vs, off);
    if ((t & 31) == 0) red[16 + (t >> 5)] = vs;
    __syncthreads();
    if (t == 0) {
        float tot = 0.0f;
        for (int w = 0; w < 8; w++) tot += red[16 + w];
        red[24] = tot;
    }
    __syncthreads();
    float var  = red[24] * (1.0f / 1024.0f);
    float rstd = rsqrtf(var + 1e-5f);

#pragma unroll
    for (int u = 0; u < 4; u++) {
        int c = t + 256 * u;
        out[(size_t)row * 1024 + c] = (x[u] - mean) * rstd * gamma[c] + beta[c];
    }
}

// ---------------------------------------------------------------------------
extern "C" void kernel_launch(void* const* d_in, const int* in_sizes, int n_in,
                              void* d_out, int out_size)
{
    const float* X     = (const float*)d_in[0];
    const float* Wq    = (const float*)d_in[1];
    const float* Wk    = (const float*)d_in[2];
    const float* Wv    = (const float*)d_in[3];
    const float* Wo    = (const float*)d_in[4];
    const float* alpha = (const float*)d_in[5];
    const float* lns   = (const float*)d_in[6];
    const float* lnb   = (const float*)d_in[7];
    float* out = (float*)d_out;

    static int attr_set = 0;
    if (!attr_set) {
        cudaFuncSetAttribute(qkv_mma,   cudaFuncAttributeMaxDynamicSharedMemorySize, DYN_SMEM);
        cudaFuncSetAttribute(oproj_mma, cudaFuncAttributeMaxDynamicSharedMemorySize, DYN_SMEM);
        attr_set = 1;
    }

    __nv_bfloat16 *Whi, *Wlo, *Xhi, *Xlo, *Woh, *Wol, *Ahi, *Alo;
    cudaGetSymbolAddress((void**)&Whi, g_Wh);
    cudaGetSymbolAddress((void**)&Wlo, g_Wl);
    cudaGetSymbolAddress((void**)&Xhi, g_Xhi);
    cudaGetSymbolAddress((void**)&Xlo, g_Xlo);
    cudaGetSymbolAddress((void**)&Woh, g_Woh);
    cudaGetSymbolAddress((void**)&Wol, g_Wol);
    cudaGetSymbolAddress((void**)&Ahi, g_Ahi);
    cudaGetSymbolAddress((void**)&Alo, g_Alo);
    float* attn_p;
    cudaGetSymbolAddress((void**)&attn_p, g_attn);

    pe_kernel<<<(SS * DKK + 255) / 256, 256>>>();
    conv_kernel<<<4096, 256>>>(X, Xhi, Xlo, MM * DD / 4);
    conv_kernel<<<1024, 256>>>(Wq, Whi,             Wlo,             DD * DD / 4);
    conv_kernel<<<1024, 256>>>(Wk, Whi + DD * DD,   Wlo + DD * DD,   DD * DD / 4);
    conv_kernel<<<1024, 256>>>(Wv, Whi + 2*DD*DD,   Wlo + 2*DD*DD,   DD * DD / 4);
    conv_kernel<<<1024, 256>>>(Wo, Woh, Wol, DD * DD / 4);

    qkv_mma<<<dim3(8, 32, 3), 256, DYN_SMEM>>>();
    smear_kernel<<<(MM * DD) / 256, 256>>>(alpha);
    attn_kernel<<<dim3(32, 32), 128>>>();
    conv_kernel<<<4096, 256>>>(attn_p, Ahi, Alo, MM * DD / 4);
    oproj_mma<<<dim3(8, 32), 256, DYN_SMEM>>>(X);
    ln_kernel<<<MM, 256>>>(lns, lnb, out);
}

// round 4
// speedup vs baseline: 2.3755x; 1.6531x over previous
#include <cuda_runtime.h>
#include <cuda_bf16.h>
#include <math.h>
#include <stdint.h>

#define BB  2
#define SS  2048
#define DD  1024
#define HH  16
#define DKK 64
#define MM  (BB*SS)   // 4096 rows

// scale folded into Q: 1/sqrt(64) * log2(e)
#define SC2 0.18033688011112042f

// ---------------------------------------------------------------------------
// Scratch (allocation-free rule: __device__ globals)
// ---------------------------------------------------------------------------
__device__ __align__(16) float g_PE[SS*DKK];
__device__ __align__(16) float g_Kraw[MM*DD];
__device__ __align__(16) float g_Y[MM*DD];

__device__ __align__(16) __nv_bfloat16 g_Xhi[MM*DD];
__device__ __align__(16) __nv_bfloat16 g_Xlo[MM*DD];
__device__ __align__(16) __nv_bfloat16 g_Wh[3*DD*DD];
__device__ __align__(16) __nv_bfloat16 g_Wl[3*DD*DD];
__device__ __align__(16) __nv_bfloat16 g_Woh[DD*DD];
__device__ __align__(16) __nv_bfloat16 g_Wol[DD*DD];
__device__ __align__(16) __nv_bfloat16 g_Ahi[MM*DD];
__device__ __align__(16) __nv_bfloat16 g_Alo[MM*DD];

// attention operands, head-split [B*H][S][64], bf16 hi/lo
__device__ __align__(16) __nv_bfloat16 g_Qhi[MM*DD];
__device__ __align__(16) __nv_bfloat16 g_Qlo[MM*DD];
__device__ __align__(16) __nv_bfloat16 g_Khi[MM*DD];
__device__ __align__(16) __nv_bfloat16 g_Klo[MM*DD];
__device__ __align__(16) __nv_bfloat16 g_Vhi[MM*DD];
__device__ __align__(16) __nv_bfloat16 g_Vlo[MM*DD];

// ---------------------------------------------------------------------------
// PTX helpers (baseline sm_103-safe)
// ---------------------------------------------------------------------------
__device__ __forceinline__ uint32_t smem_u32(const void* p) {
    uint32_t a;
    asm("{ .reg .u64 t; cvta.to.shared.u64 t, %1; cvt.u32.u64 %0, t; }"
        : "=r"(a) : "l"(p));
    return a;
}

#define CPA16(dst, src) \
    asm volatile("cp.async.cg.shared.global [%0], [%1], 16;" :: "r"(dst), "l"(src) : "memory")
#define CPA_COMMIT() asm volatile("cp.async.commit_group;" ::: "memory")
#define CPA_WAIT1()  asm volatile("cp.async.wait_group 1;" ::: "memory")
#define CPA_WAIT0()  asm volatile("cp.async.wait_group 0;" ::: "memory")

__device__ __forceinline__ void ldsm_x4(uint32_t* r, uint32_t addr) {
    asm volatile("ldmatrix.sync.aligned.m8n8.x4.shared.b16 {%0,%1,%2,%3}, [%4];"
                 : "=r"(r[0]), "=r"(r[1]), "=r"(r[2]), "=r"(r[3]) : "r"(addr));
}
__device__ __forceinline__ void ldsm_x4_t(uint32_t* r, uint32_t addr) {
    asm volatile("ldmatrix.sync.aligned.m8n8.x4.trans.shared.b16 {%0,%1,%2,%3}, [%4];"
                 : "=r"(r[0]), "=r"(r[1]), "=r"(r[2]), "=r"(r[3]) : "r"(addr));
}

__device__ __forceinline__ void mma_bf16(float* c, const uint32_t* a, const uint32_t* b) {
    asm volatile(
        "mma.sync.aligned.m16n8k16.row.col.f32.bf16.bf16.f32 "
        "{%0,%1,%2,%3}, {%4,%5,%6,%7}, {%8,%9}, {%0,%1,%2,%3};"
        : "+f"(c[0]), "+f"(c[1]), "+f"(c[2]), "+f"(c[3])
        : "r"(a[0]), "r"(a[1]), "r"(a[2]), "r"(a[3]), "r"(b[0]), "r"(b[1]));
}

__device__ __forceinline__ float ex2(float x) {
    float r;
    asm("ex2.approx.ftz.f32 %0, %1;" : "=f"(r) : "f"(x));
    return r;
}
// pack two fp32 -> bf16x2 reg  (lo half = a, hi half = b)
__device__ __forceinline__ uint32_t pk_bf2(float a, float b) {
    uint32_t r;
    asm("cvt.rn.bf16x2.f32 %0, %1, %2;" : "=r"(r) : "f"(b), "f"(a));
    return r;
}
__device__ __forceinline__ float bf_lo(uint32_t r) { return __uint_as_float(r << 16); }
__device__ __forceinline__ float bf_hi(uint32_t r) { return __uint_as_float(r & 0xFFFF0000u); }

// ---------------------------------------------------------------------------
__global__ void pe_kernel() {
    int idx = blockIdx.x * blockDim.x + threadIdx.x;
    if (idx >= SS * DKK) return;
    int s  = idx >> 6;
    int dk = idx & 63;
    int i  = dk >> 1;
    float freq = expf(-((float)(2 * i) / 64.0f) * 9.210340371976184f);
    float ang  = (float)s * freq;
    g_PE[idx]  = (dk & 1) ? cosf(ang) : sinf(ang);
}

// ---------------------------------------------------------------------------
// fp32 -> bf16 hi/lo split
// ---------------------------------------------------------------------------
__global__ void conv_kernel(const float* __restrict__ src,
                            __nv_bfloat16* __restrict__ hi,
                            __nv_bfloat16* __restrict__ lo, int n4) {
    int i = blockIdx.x * blockDim.x + threadIdx.x;
    if (i >= n4) return;
    float4 v = ((const float4*)src)[i];
    __nv_bfloat16 h0 = __float2bfloat16(v.x);
    __nv_bfloat16 h1 = __float2bfloat16(v.y);
    __nv_bfloat16 h2 = __float2bfloat16(v.z);
    __nv_bfloat16 h3 = __float2bfloat16(v.w);
    __nv_bfloat16 l0 = __float2bfloat16(v.x - __bfloat162float(h0));
    __nv_bfloat16 l1 = __float2bfloat16(v.y - __bfloat162float(h1));
    __nv_bfloat16 l2 = __float2bfloat16(v.z - __bfloat162float(h2));
    __nv_bfloat16 l3 = __float2bfloat16(v.w - __bfloat162float(h3));
    __nv_bfloat162* hp = (__nv_bfloat162*)hi;
    __nv_bfloat162* lp = (__nv_bfloat162*)lo;
    hp[2*i]   = __nv_bfloat162(h0, h1);
    hp[2*i+1] = __nv_bfloat162(h2, h3);
    lp[2*i]   = __nv_bfloat162(l0, l1);
    lp[2*i+1] = __nv_bfloat162(l2, l3);
}

// ---------------------------------------------------------------------------
// bf16x3 HMMA GEMM mainloop (unchanged from R3)
// ---------------------------------------------------------------------------
#define ROWB 80
#define MATB (128 * ROWB)
#define STG  (4 * MATB)
#define DYN_SMEM (2 * STG)

__device__ __forceinline__ void mma_gemm(
    const __nv_bfloat16* __restrict__ Ah, const __nv_bfloat16* __restrict__ Al,
    const __nv_bfloat16* __restrict__ Bh, const __nv_bfloat16* __restrict__ Bl,
    char* dyn, float acc[2][8][4])
{
    int t    = threadIdx.x;
    int lane = t & 31;
    int wid  = t >> 5;
    int wm   = wid >> 1;
    int wn   = wid & 1;
    uint32_t sbase = smem_u32(dyn);

    const char* mats[4] = {(const char*)Ah, (const char*)Al,
                           (const char*)Bh, (const char*)Bl};

#pragma unroll
    for (int tm = 0; tm < 2; tm++)
#pragma unroll
        for (int tn = 0; tn < 8; tn++)
#pragma unroll
            for (int u = 0; u < 4; u++) acc[tm][tn][u] = 0.0f;

    int idx0 = t * 8;
    auto load_stage = [&](int st, int kb) {
        uint32_t stb = sbase + st * STG;
#pragma unroll
        for (int q = 0; q < 8; q++) {
            int idx = idx0 + q;
            int mat = idx >> 9;
            int r   = (idx >> 2) & 127;
            int c16 = idx & 3;
            uint32_t dst = stb + mat * MATB + r * ROWB + c16 * 16;
            const char* src = mats[mat] + ((size_t)r * 1024 + kb + c16 * 8) * 2;
            CPA16(dst, src);
        }
        CPA_COMMIT();
    };

    int a_row = wm * 32 + (lane & 15);
    int b_row = wn * 64 + (lane & 7) + 8 * (lane >> 4);

    load_stage(0, 0);

    for (int it = 0; it < 32; it++) {
        int st = it & 1;
        if (it + 1 < 32) {
            load_stage(st ^ 1, (it + 1) * 32);
            CPA_WAIT1();
        } else {
            CPA_WAIT0();
        }
        __syncthreads();

        uint32_t stb = sbase + st * STG;
#pragma unroll
        for (int ks = 0; ks < 2; ks++) {
            int k0 = ks * 16;
            uint32_t aH[2][4], aL[2][4], bH[8][2], bL[8][2];
            int a_col = (k0 + 8 * (lane >> 4)) * 2;
            int b_col = (k0 + 8 * ((lane >> 3) & 1)) * 2;
#pragma unroll
            for (int tm = 0; tm < 2; tm++) {
                uint32_t off = (uint32_t)((a_row + 16 * tm) * ROWB + a_col);
                ldsm_x4(aH[tm], stb + 0 * MATB + off);
                ldsm_x4(aL[tm], stb + 1 * MATB + off);
            }
#pragma unroll
            for (int tp = 0; tp < 4; tp++) {
                uint32_t off = (uint32_t)((b_row + 16 * tp) * ROWB + b_col);
                ldsm_x4(&bH[2 * tp][0], stb + 2 * MATB + off);
                ldsm_x4(&bL[2 * tp][0], stb + 3 * MATB + off);
            }
#pragma unroll
            for (int tm = 0; tm < 2; tm++)
#pragma unroll
                for (int tn = 0; tn < 8; tn++) {
                    mma_bf16(acc[tm][tn], aH[tm], bH[tn]);
                    mma_bf16(acc[tm][tn], aH[tm], bL[tn]);
                    mma_bf16(acc[tm][tn], aL[tm], bH[tn]);
                }
        }
        __syncthreads();
    }
}

// ---------------------------------------------------------------------------
// QKV GEMM. z=0: Q -> (acc+PE)*SC2 split to g_Qhi/g_Qlo (bf16, head-split)
//           z=1: K -> g_Kraw fp32 (head-split)
//           z=2: V -> split to g_Vhi/g_Vlo
// ---------------------------------------------------------------------------
__global__ __launch_bounds__(256) void qkv_mma() {
    extern __shared__ char dyn[];
    float acc[2][8][4];

    int z  = blockIdx.z;
    int m0 = blockIdx.y * 128;
    int n0 = blockIdx.x * 128;

    mma_gemm(g_Xhi + (size_t)m0 * 1024, g_Xlo + (size_t)m0 * 1024,
             g_Wh + (size_t)z * DD * DD + (size_t)n0 * 1024,
             g_Wl + (size_t)z * DD * DD + (size_t)n0 * 1024,
             dyn, acc);

    int t = threadIdx.x, lane = t & 31, wid = t >> 5;
    int wm = wid >> 1, wn = wid & 1;

#pragma unroll
    for (int tm = 0; tm < 2; tm++)
#pragma unroll
        for (int tn = 0; tn < 8; tn++) {
            int c  = n0 + wn * 64 + tn * 8 + (lane & 3) * 2;
            int h  = c >> 6, dk = c & 63;
#pragma unroll
            for (int half = 0; half < 2; half++) {
                int m = m0 + wm * 32 + tm * 16 + (lane >> 2) + 8 * half;
                int b = m >> 11, s = m & 2047;
                float vx = acc[tm][tn][2 * half + 0];
                float vy = acc[tm][tn][2 * half + 1];
                size_t off = ((size_t)((b * 16 + h) * 2048 + s)) * 64 + dk;
                if (z == 1) {
                    float2 v; v.x = vx; v.y = vy;
                    *(float2*)&g_Kraw[off] = v;
                } else {
                    if (z == 0) {
                        float2 pe = *(const float2*)&g_PE[s * 64 + dk];
                        vx = (vx + pe.x) * SC2;
                        vy = (vy + pe.y) * SC2;
                    }
                    __nv_bfloat16 hx = __float2bfloat16(vx);
                    __nv_bfloat16 hy = __float2bfloat16(vy);
                    __nv_bfloat16 lx = __float2bfloat16(vx - __bfloat162float(hx));
                    __nv_bfloat16 ly = __float2bfloat16(vy - __bfloat162float(hy));
                    __nv_bfloat162* oh = (__nv_bfloat162*)((z == 0) ? g_Qhi : g_Vhi);
                    __nv_bfloat162* ol = (__nv_bfloat162*)((z == 0) ? g_Qlo : g_Vlo);
                    oh[off >> 1] = __nv_bfloat162(hx, hy);
                    ol[off >> 1] = __nv_bfloat162(lx, ly);
                }
            }
        }
}

// ---------------------------------------------------------------------------
// EMA smear on K + PE add, output split to bf16 hi/lo
// ---------------------------------------------------------------------------
__global__ void smear_kernel(const float* __restrict__ alpha) {
    int idx = blockIdx.x * blockDim.x + threadIdx.x;
    int dk = idx & 63;
    int s  = (idx >> 6) & 2047;
    int h  = (idx >> 17) & 15;
    float kc = g_Kraw[idx];
    float v;
    if (s == 0) {
        v = kc;
    } else {
        float a = 1.0f / (1.0f + expf(-alpha[h * 2047 + (s - 1)]));
        v = a * kc + (1.0f - a) * g_Kraw[idx - 64];
    }
    v += g_PE[s * 64 + dk];
    __nv_bfloat16 hv = __float2bfloat16(v);
    g_Khi[idx] = hv;
    g_Klo[idx] = __float2bfloat16(v - __bfloat162float(hv));
}

// ---------------------------------------------------------------------------
// Causal flash attention, bf16x3 HMMA. BM=64, BN=64, 128 threads (4 warps).
// Warp w owns q rows [qb + 16w, +16). Smem: 4 mats x 64 rows x 144B.
// Q pre-scaled by 0.125*log2e -> softmax in base 2.
// Output written directly as bf16 hi/lo (A operand of the O-projection).
// ---------------------------------------------------------------------------
#define ASTR 144
#define AMAT (64 * ASTR)   // 9216

__global__ __launch_bounds__(128) void attn_mma() {
    __shared__ __align__(16) char sm[4 * AMAT];
    uint32_t sb = smem_u32(sm);

    int t = threadIdx.x, lane = t & 31, w = t >> 5;
    int qt = 31 - (int)blockIdx.x;          // heavy tiles first
    int qb = qt * 64;
    int bh = blockIdx.y;
    size_t base = (size_t)bh * SS * DKK;

    // ---- stage Q tile (hi -> mat0, lo -> mat1), extract A-frags ----
    {
        const char* qsrc[2] = {(const char*)(g_Qhi + base), (const char*)(g_Qlo + base)};
#pragma unroll
        for (int q = 0; q < 8; q++) {
            int idx = t * 8 + q;
            int mat = idx >> 9;
            int r   = (idx >> 3) & 63;
            int c   = idx & 7;
            CPA16(sb + mat * AMAT + r * ASTR + c * 16,
                  qsrc[mat] + ((size_t)(qb + r) * 64 + c * 8) * 2);
        }
        CPA_COMMIT(); CPA_WAIT0();
        __syncthreads();
    }

    uint32_t qh[4][4], ql[4][4];
    {
        int ar = w * 16 + (lane & 15);
#pragma unroll
        for (int k = 0; k < 4; k++) {
            uint32_t acol = (uint32_t)(k * 32 + (lane >> 4) * 16);
            ldsm_x4(qh[k], sb + 0 * AMAT + ar * ASTR + acol);
            ldsm_x4(ql[k], sb + 1 * AMAT + ar * ASTR + acol);
        }
    }

    float o[8][4];
    float m2[2], lsum[2];
#pragma unroll
    for (int j = 0; j < 8; j++)
#pragma unroll
        for (int u = 0; u < 4; u++) o[j][u] = 0.0f;
    m2[0] = m2[1] = -1e30f;
    lsum[0] = lsum[1] = 0.0f;

    const char* kvsrc[4] = {(const char*)(g_Khi + base), (const char*)(g_Klo + base),
                            (const char*)(g_Vhi + base), (const char*)(g_Vlo + base)};

    int r0 = (lane >> 2);         // row within 16-row warp tile (plus 8 for half 1)
    int ntiles = qt + 1;

    for (int tile = 0; tile < ntiles; tile++) {
        int kb = tile * 64;
        __syncthreads();           // previous compute done before overwrite
#pragma unroll
        for (int q = 0; q < 16; q++) {
            int idx = t * 16 + q;
            int mat = idx >> 9;
            int r   = (idx >> 3) & 63;
            int c   = idx & 7;
            CPA16(sb + mat * AMAT + r * ASTR + c * 16,
                  kvsrc[mat] + ((size_t)(kb + r) * 64 + c * 8) * 2);
        }
        CPA_COMMIT(); CPA_WAIT0();
        __syncthreads();

        // ---- S = Q K^T (bf16x3) ----
        float s[8][4];
#pragma unroll
        for (int j = 0; j < 8; j++)
#pragma unroll
            for (int u = 0; u < 4; u++) s[j][u] = 0.0f;

        {
            int b_row = (lane & 7) + 8 * (lane >> 4);
#pragma unroll
            for (int k = 0; k < 4; k++) {
                uint32_t bcol = (uint32_t)((k * 16 + 8 * ((lane >> 3) & 1)) * 2);
                uint32_t kH[8][2], kL[8][2];
#pragma unroll
                for (int tp = 0; tp < 4; tp++) {
                    uint32_t off = (uint32_t)((b_row + 16 * tp) * ASTR) + bcol;
                    ldsm_x4(&kH[2 * tp][0], sb + 0 * AMAT + off);
                    ldsm_x4(&kL[2 * tp][0], sb + 1 * AMAT + off);
                }
#pragma unroll
                for (int j = 0; j < 8; j++) {
                    mma_bf16(s[j], qh[k], kH[j]);
                    mma_bf16(s[j], qh[k], kL[j]);
                    mma_bf16(s[j], ql[k], kH[j]);
                }
            }
        }

        // ---- mask (diagonal tile) ----
        if (tile == ntiles - 1) {
#pragma unroll
            for (int j = 0; j < 8; j++)
#pragma unroll
                for (int u = 0; u < 4; u++) {
                    int row = (w * 16) + r0 + 8 * (u >> 1);          // within 64
                    int col = j * 8 + 2 * (lane & 3) + (u & 1);
                    if (col > row) s[j][u] = -1e30f;
                }
        }

        // ---- online softmax (base 2), per row half ----
#pragma unroll
        for (int h = 0; h < 2; h++) {
            float mx = -1e30f;
#pragma unroll
            for (int j = 0; j < 8; j++) {
                mx = fmaxf(mx, s[j][2 * h + 0]);
                mx = fmaxf(mx, s[j][2 * h + 1]);
            }
            mx = fmaxf(mx, __shfl_xor_sync(0xffffffffu, mx, 1));
            mx = fmaxf(mx, __shfl_xor_sync(0xffffffffu, mx, 2));
            float mnew = fmaxf(m2[h], mx);
            float corr = ex2(m2[h] - mnew);
            m2[h] = mnew;
            float rs = 0.0f;
#pragma unroll
            for (int j = 0; j < 8; j++) {
                float p0 = ex2(s[j][2 * h + 0] - mnew);
                float p1 = ex2(s[j][2 * h + 1] - mnew);
                s[j][2 * h + 0] = p0;
                s[j][2 * h + 1] = p1;
                rs += p0 + p1;
            }
            lsum[h] = lsum[h] * corr + rs;
#pragma unroll
            for (int j = 0; j < 8; j++) {
                o[j][2 * h + 0] *= corr;
                o[j][2 * h + 1] *= corr;
            }
        }

        // ---- P fragments (C->A remap, hi/lo split in registers) ----
        uint32_t pH[4][4], pL[4][4];
#pragma unroll
        for (int kk = 0; kk < 4; kk++) {
            int j = 2 * kk;
#pragma unroll
            for (int q = 0; q < 4; q++) {
                int jj = j + (q >> 1);
                float a = s[jj][(q & 1) * 2 + 0];
                float b = s[jj][(q & 1) * 2 + 1];
                uint32_t hi2 = pk_bf2(a, b);
                pH[kk][q] = hi2;
                pL[kk][q] = pk_bf2(a - bf_lo(hi2), b - bf_hi(hi2));
            }
        }

        // ---- O += P V (bf16x3), V via ldmatrix.trans ----
        {
            int vrow = (lane & 7) + 8 * ((lane >> 3) & 1);
            uint32_t vcol = (uint32_t)(16 * (lane >> 4));
#pragma unroll
            for (int kk = 0; kk < 4; kk++) {
                uint32_t vH[8][2], vL[8][2];
#pragma unroll
                for (int jj = 0; jj < 4; jj++) {
                    uint32_t off = (uint32_t)((kk * 16 + vrow) * ASTR) + (uint32_t)(jj * 32) + vcol;
                    ldsm_x4_t(&vH[2 * jj][0], sb + 2 * AMAT + off);
                    ldsm_x4_t(&vL[2 * jj][0], sb + 3 * AMAT + off);
                }
#pragma unroll
                for (int j = 0; j < 8; j++) {
                    mma_bf16(o[j], pH[kk], vH[j]);
                    mma_bf16(o[j], pL[kk], vH[j]);
                    mma_bf16(o[j], pH[kk], vL[j]);
                }
            }
        }
    }

    // ---- epilogue: normalize, split to bf16 hi/lo, store ----
#pragma unroll
    for (int h = 0; h < 2; h++) {
        lsum[h] += __shfl_xor_sync(0xffffffffu, lsum[h], 1);
        lsum[h] += __shfl_xor_sync(0xffffffffu, lsum[h], 2);
        lsum[h] = 1.0f / lsum[h];
    }

    int b = bh >> 4, hh = bh & 15;
#pragma unroll
    for (int j = 0; j < 8; j++) {
        int dk = j * 8 + 2 * (lane & 3);
#pragma unroll
        for (int h = 0; h < 2; h++) {
            int srow = qb + w * 16 + r0 + 8 * h;
            float f0 = o[j][2 * h + 0] * lsum[h];
            float f1 = o[j][2 * h + 1] * lsum[h];
            __nv_bfloat16 h0 = __float2bfloat16(f0);
            __nv_bfloat16 h1 = __float2bfloat16(f1);
            __nv_bfloat16 l0 = __float2bfloat16(f0 - __bfloat162float(h0));
            __nv_bfloat16 l1 = __float2bfloat16(f1 - __bfloat162float(h1));
            size_t off = ((size_t)(b * SS + srow) * DD + hh * 64 + dk) >> 1;
            ((__nv_bfloat162*)g_Ahi)[off] = __nv_bfloat162(h0, h1);
            ((__nv_bfloat162*)g_Alo)[off] = __nv_bfloat162(l0, l1);
        }
    }
}

// ---------------------------------------------------------------------------
// Output projection GEMM: Y = attn @ Wo^T + X
// ---------------------------------------------------------------------------
__global__ __launch_bounds__(256) void oproj_mma(const float* __restrict__ X) {
    extern __shared__ char dyn[];
    float acc[2][8][4];

    int m0 = blockIdx.y * 128;
    int n0 = blockIdx.x * 128;

    mma_gemm(g_Ahi + (size_t)m0 * 1024, g_Alo + (size_t)m0 * 1024,
             g_Woh + (size_t)n0 * 1024, g_Wol + (size_t)n0 * 1024,
             dyn, acc);

    int t = threadIdx.x, lane = t & 31, wid = t >> 5;
    int wm = wid >> 1, wn = wid & 1;
#pragma unroll
    for (int tm = 0; tm < 2; tm++)
#pragma unroll
        for (int tn = 0; tn < 8; tn++) {
            int c = n0 + wn * 64 + tn * 8 + (lane & 3) * 2;
#pragma unroll
            for (int half = 0; half < 2; half++) {
                int m = m0 + wm * 32 + tm * 16 + (lane >> 2) + 8 * half;
                float2 xr = *(const float2*)&X[(size_t)m * 1024 + c];
                float2 v;
                v.x = acc[tm][tn][2 * half + 0] + xr.x;
                v.y = acc[tm][tn][2 * half + 1] + xr.y;
                *(float2*)&g_Y[(size_t)m * 1024 + c] = v;
            }
        }
}

// ---------------------------------------------------------------------------
// LayerNorm over D=1024 per row
// ---------------------------------------------------------------------------
__global__ void ln_kernel(const float* __restrict__ gamma,
                          const float* __restrict__ beta,
                          float* __restrict__ out)
{
    int row = blockIdx.x;
    int t   = threadIdx.x;
    const float* y = g_Y + (size_t)row * 1024;

    float x[4];
    float s = 0.0f;
#pragma unroll
    for (int u = 0; u < 4; u++) { x[u] = y[t + 256 * u]; s += x[u]; }

    __shared__ float red[32];
#pragma unroll
    for (int off = 16; off; off >>= 1) s += __shfl_xor_sync(0xffffffffu, s, off);
    if ((t & 31) == 0) red[t >> 5] = s;
    __syncthreads();
    if (t == 0) {
        float tot = 0.0f;
        for (int w = 0; w < 8; w++) tot += red[w];
        red[8] = tot;
    }
    __syncthreads();
    float mean = red[8] * (1.0f / 1024.0f);

    float vs = 0.0f;
#pragma unroll
    for (int u = 0; u < 4; u++) { float d = x[u] - mean; vs += d * d; }
#pragma unroll
    for (int off = 16; off; off >>= 1) vs += __shfl_xor_sync(0xffffffffu, vs, off);
    if ((t & 31) == 0) red[16 + (t >> 5)] = vs;
    __syncthreads();
    if (t == 0) {
        float tot = 0.0f;
        for (int w = 0; w < 8; w++) tot += red[16 + w];
        red[24] = tot;
    }
    __syncthreads();
    float var  = red[24] * (1.0f / 1024.0f);
    float rstd = rsqrtf(var + 1e-5f);

#pragma unroll
    for (int u = 0; u < 4; u++) {
        int c = t + 256 * u;
        out[(size_t)row * 1024 + c] = (x[u] - mean) * rstd * gamma[c] + beta[c];
    }
}

// ---------------------------------------------------------------------------
extern "C" void kernel_launch(void* const* d_in, const int* in_sizes, int n_in,
                              void* d_out, int out_size)
{
    const float* X     = (const float*)d_in[0];
    const float* Wq    = (const float*)d_in[1];
    const float* Wk    = (const float*)d_in[2];
    const float* Wv    = (const float*)d_in[3];
    const float* Wo    = (const float*)d_in[4];
    const float* alpha = (const float*)d_in[5];
    const float* lns   = (const float*)d_in[6];
    const float* lnb   = (const float*)d_in[7];
    float* out = (float*)d_out;

    static int attr_set = 0;
    if (!attr_set) {
        cudaFuncSetAttribute(qkv_mma,   cudaFuncAttributeMaxDynamicSharedMemorySize, DYN_SMEM);
        cudaFuncSetAttribute(oproj_mma, cudaFuncAttributeMaxDynamicSharedMemorySize, DYN_SMEM);
        attr_set = 1;
    }

    __nv_bfloat16 *Whi, *Wlo, *Xhi, *Xlo, *Woh, *Wol;
    cudaGetSymbolAddress((void**)&Whi, g_Wh);
    cudaGetSymbolAddress((void**)&Wlo, g_Wl);
    cudaGetSymbolAddress((void**)&Xhi, g_Xhi);
    cudaGetSymbolAddress((void**)&Xlo, g_Xlo);
    cudaGetSymbolAddress((void**)&Woh, g_Woh);
    cudaGetSymbolAddress((void**)&Wol, g_Wol);

    pe_kernel<<<(SS * DKK + 255) / 256, 256>>>();
    conv_kernel<<<4096, 256>>>(X, Xhi, Xlo, MM * DD / 4);
    conv_kernel<<<1024, 256>>>(Wq, Whi,             Wlo,             DD * DD / 4);
    conv_kernel<<<1024, 256>>>(Wk, Whi + DD * DD,   Wlo + DD * DD,   DD * DD / 4);
    conv_kernel<<<1024, 256>>>(Wv, Whi + 2*DD*DD,   Wlo + 2*DD*DD,   DD * DD / 4);
    conv_kernel<<<1024, 256>>>(Wo, Woh, Wol, DD * DD / 4);

    qkv_mma<<<dim3(8, 32, 3), 256, DYN_SMEM>>>();
    smear_kernel<<<(MM * DD) / 256, 256>>>(alpha);
    attn_mma<<<dim3(32, 32), 128>>>();
    oproj_mma<<<dim3(8, 32), 256, DYN_SMEM>>>(X);
    ln_kernel<<<MM, 256>>>(lns, lnb, out);
}